// round 13
// baseline (speedup 1.0000x reference)
#include <cuda_runtime.h>

// ASTGC_37976100831379 — R8 (FINAL, converged configuration)
//
// Dead-graph analysis (bitwise-verified rel_err=0.0 on every passing round):
// the reference returns fusion_out[:, 0] — the star-graph hub node, which
// receives no messages (its row of the concat is an explicit zeros tensor).
// Hence the entire upstream graph (both TCN branches, the O(B*N^2*H) GCN
// edge aggregation over 32,896 edges, the fusion GEMMs, the cross-batch
// softmax attention) is dead code, and
//
//     out[b, s, 0] = fgcn_b[s]      b in [0,32), s in [0,48)
//
// i.e. a 192 B -> 6 KB broadcast. Measured evidence of convergence:
//   - grid sweep 1/4/6/8/16 -> kernel 4.38/4.26/3.65/3.52/3.81 us
//   - identical-binary repeat at grid=8 -> dur_us {4.61, 5.98}
// Within-config noise (±1 us) >= between-config spread: this is the
// graph-replay launch floor. DRAM/issue utilization ~0% throughout.
//
// Configuration: grid=8, block (12,4); tx = float4 col, row = bx*4+ty.
// Per thread: one LDG.128 from bias4[tx] (zero arithmetic on the load path,
// 12 distinct addresses fully merged in L1/L2) + one STG.128, contiguous
// per warp.

#define ASTGC_S 48

__global__ void __launch_bounds__(48, 1)
astgc_bias_broadcast_final(const float4* __restrict__ bias4,
                           float4* __restrict__ out4) {
    unsigned tx  = threadIdx.x;                            // 0..11 (float4 col)
    unsigned row = blockIdx.x * blockDim.y + threadIdx.y;  // 0..31 (batch)
    out4[row * 12u + tx] = bias4[tx];
}

extern "C" void kernel_launch(void* const* d_in, const int* in_sizes, int n_in,
                              void* d_out, int out_size) {
    // Locate fgcn_b: the unique input with exactly S=48 elements.
    // (All other biases are 64 or 1 elements; fgcn_w is 64*48=3072.)
    int bias_idx = -1;
    for (int i = 0; i < n_in; ++i) {
        if (in_sizes[i] == ASTGC_S) { bias_idx = i; break; }
    }
    if (bias_idx < 0) bias_idx = 30;  // setup_inputs order fallback

    const float4* bias4 = (const float4*)d_in[bias_idx];
    float4* out4 = (float4*)d_out;

    dim3 block(12, 4);   // 48 threads
    dim3 grid(8);        // 8 * 4 = 32 batch rows
    astgc_bias_broadcast_final<<<grid, block>>>(bias4, out4);
}

// round 14
// speedup vs baseline: 1.2983x; 1.2983x over previous
#include <cuda_runtime.h>

// ASTGC_37976100831379 — R9 (converged; identical-binary repeat #4)
//
// Dead-graph analysis (bitwise rel_err=0.0 every passing round): the
// reference returns fusion_out[:, 0] — the star-graph hub node, which
// receives no messages (its concat row is an explicit zeros tensor). The
// entire upstream graph (both TCNs, the O(B*N^2*H) GCN edge aggregation,
// fusion GEMMs, cross-batch softmax) is dead code:
//
//     out[b, s, 0] = fgcn_b[s]      b in [0,32), s in [0,48)
//
// -> 192 B -> 6 KB broadcast; one graph node; DRAM/issue ~0%.
//
// Convergence evidence:
//   grid sweep 1/4/6/8/16 -> kernel 4.38/4.26/3.65/3.52/3.81 us
//   identical grid=8 binary, 3 sessions -> dur_us 4.61/5.98/7.52
//     (ncu 3.52/4.03/4.48: monotone session drift on unchanged SASS =
//      @NAT clock/container state, not code). Session noise >> any code
//      delta; this is the graph-replay launch floor.
//
// Config: grid=8, block (12,4). Per thread: LDG.128 bias4[tx] (zero load-
// path arithmetic, 12 distinct fully-merged addresses) + contiguous STG.128.

#define ASTGC_S 48

__global__ void __launch_bounds__(48, 1)
astgc_bias_broadcast_final(const float4* __restrict__ bias4,
                           float4* __restrict__ out4) {
    unsigned tx  = threadIdx.x;                            // 0..11 (float4 col)
    unsigned row = blockIdx.x * blockDim.y + threadIdx.y;  // 0..31 (batch)
    out4[row * 12u + tx] = bias4[tx];
}

extern "C" void kernel_launch(void* const* d_in, const int* in_sizes, int n_in,
                              void* d_out, int out_size) {
    // Locate fgcn_b: the unique input with exactly S=48 elements.
    int bias_idx = -1;
    for (int i = 0; i < n_in; ++i) {
        if (in_sizes[i] == ASTGC_S) { bias_idx = i; break; }
    }
    if (bias_idx < 0) bias_idx = 30;  // setup_inputs order fallback

    const float4* bias4 = (const float4*)d_in[bias_idx];
    float4* out4 = (float4*)d_out;

    dim3 block(12, 4);   // 48 threads
    dim3 grid(8);        // 8 * 4 = 32 batch rows
    astgc_bias_broadcast_final<<<grid, block>>>(bias4, out4);
}

// round 15
// speedup vs baseline: 1.6434x; 1.2657x over previous
#include <cuda_runtime.h>

// ASTGC_37976100831379 — R10 (CONVERGED; identical-binary repeat #5)
//
// Dead-graph analysis (bitwise rel_err=0.0 on every passing round): the
// reference returns fusion_out[:, 0] — the star-graph hub node, which
// receives no messages (its concat row is an explicit zeros tensor). The
// entire upstream graph (both TCN branches, the O(B*N^2*H) GCN edge
// aggregation over 32,896 edges, the fusion GEMMs, the cross-batch softmax
// attention) is dead code with respect to the output:
//
//     out[b, s, 0] = fgcn_b[s]      b in [0,32), s in [0,48)
//
// -> a 192 B -> 6 KB broadcast; one graph node; DRAM/issue ~0%.
//
// Convergence evidence:
//   grid sweep 1/4/6/8/16  -> ncu kernel 4.38/4.26/3.65/3.52/3.81 us
//   identical grid=8 binary, 4 sessions -> dur_us 4.61/5.98/7.52/5.79
//     (ncu 3.52/4.03/4.48/3.78 on unchanged SASS = @NAT clock/session
//      state). Session noise (±1.5 us) >> any achievable code delta:
//      this is the graph-replay launch floor.
//
// Config: grid=8, block (12,4). Per thread: one LDG.128 from bias4[tx]
// (zero load-path arithmetic; 12 distinct, fully L1/L2-merged addresses)
// + one contiguous STG.128.

#define ASTGC_S 48

__global__ void __launch_bounds__(48, 1)
astgc_bias_broadcast_final(const float4* __restrict__ bias4,
                           float4* __restrict__ out4) {
    unsigned tx  = threadIdx.x;                            // 0..11 (float4 col)
    unsigned row = blockIdx.x * blockDim.y + threadIdx.y;  // 0..31 (batch)
    out4[row * 12u + tx] = bias4[tx];
}

extern "C" void kernel_launch(void* const* d_in, const int* in_sizes, int n_in,
                              void* d_out, int out_size) {
    // Locate fgcn_b: the unique input with exactly S=48 elements.
    // (All other biases have 64 or 1 elements; fgcn_w is 64*48=3072.)
    int bias_idx = -1;
    for (int i = 0; i < n_in; ++i) {
        if (in_sizes[i] == ASTGC_S) { bias_idx = i; break; }
    }
    if (bias_idx < 0) bias_idx = 30;  // setup_inputs order fallback

    const float4* bias4 = (const float4*)d_in[bias_idx];
    float4* out4 = (float4*)d_out;

    dim3 block(12, 4);   // 48 threads
    dim3 grid(8);        // 8 * 4 = 32 batch rows
    astgc_bias_broadcast_final<<<grid, block>>>(bias4, out4);
}